// round 12
// baseline (speedup 1.0000x reference)
#include <cuda_runtime.h>
#include <cuda_bf16.h>
#include <math.h>
#include <stdint.h>

#define D 512
#define Bsz 16
#define L 2048
#define HID 2048
#define GH 128
#define NTOK (Bsz * L)   // 32768

typedef __nv_bfloat16 bf16;
typedef __nv_bfloat162 bf162;

// ------------------------- scratch (static device globals) -------------------------
__device__ bf16  g_h[(size_t)NTOK * D];    // ln2 out
__device__ bf16  g_gm[(size_t)NTOK * D];   // gelu(conv mix)
__device__ bf16  g_m2[(size_t)NTOK * D];   // mixed2
__device__ float g_x1[(size_t)NTOK * D];   // first residual out
__device__ bf16  g_t[(size_t)NTOK * HID];  // ffn hidden
__device__ bf16  g_wmixB[D * D];
__device__ bf16  g_woutT[D * D];
__device__ bf16  g_w1T[HID * D];
__device__ bf16  g_w2T[D * HID];
__device__ float g_ct[Bsz * D];            // column sums (atomic)
__device__ float g_gate[Bsz * D];

// fast tanh-form GELU, scalar fp32 (deviation ~1e-3 vs erf; attenuated downstream)
__device__ __forceinline__ float gelu_fast(float v) {
    float t = v * (1.5957692f + 0.07135481f * v * v);
    return __fdividef(v, 1.0f + __expf(-t));
}
// packed bf16x2 tanh-form GELU (one ex2.bf16x2 + one div for 2 values)
__device__ __forceinline__ bf162 gelu2(bf162 v) {
    const bf162 c0 = __float2bfloat162_rn(1.5957692f);
    const bf162 c1 = __float2bfloat162_rn(0.07135481f);
    const bf162 one = __float2bfloat162_rn(1.0f);
    bf162 v2 = __hmul2(v, v);
    bf162 t = __hmul2(v, __hfma2(c1, v2, c0));
    bf162 e = h2exp(__hneg2(t));
    return __h2div(v, __hadd2(one, e));
}
__device__ __forceinline__ uint32_t smem_u32(const void* p) {
    uint32_t a;
    asm("{ .reg .u64 t; cvta.to.shared.u64 t, %1; cvt.u32.u64 %0, t; }" : "=r"(a) : "l"(p));
    return a;
}
__device__ __forceinline__ void cpasync16(uint32_t s, const void* g) {
    asm volatile("cp.async.cg.shared.global [%0], [%1], 16;" :: "r"(s), "l"(g));
}
__device__ __forceinline__ void cp_commit() { asm volatile("cp.async.commit_group;"); }
template <int N>
__device__ __forceinline__ void cp_wait() {
    asm volatile("cp.async.wait_group %0;" :: "n"(N));
}
__device__ __forceinline__ void ldmat4(uint32_t* r, uint32_t addr) {
    asm volatile("ldmatrix.sync.aligned.m8n8.x4.shared.b16 {%0,%1,%2,%3}, [%4];"
                 : "=r"(r[0]), "=r"(r[1]), "=r"(r[2]), "=r"(r[3]) : "r"(addr));
}
__device__ __forceinline__ void mma16816(float* c, const uint32_t* a, uint32_t b0,
                                         uint32_t b1) {
    asm volatile(
        "mma.sync.aligned.m16n8k16.row.col.f32.bf16.bf16.f32 "
        "{%0,%1,%2,%3}, {%4,%5,%6,%7}, {%8,%9}, {%0,%1,%2,%3};"
        : "+f"(c[0]), "+f"(c[1]), "+f"(c[2]), "+f"(c[3])
        : "r"(a[0]), "r"(a[1]), "r"(a[2]), "r"(a[3]), "r"(b0), "r"(b1));
}
__device__ __forceinline__ uint32_t mulbf2(uint32_t x, bf162 g) {
    bf162 v = *reinterpret_cast<bf162*>(&x);
    v = __hmul2(v, g);
    return *reinterpret_cast<uint32_t*>(&v);
}

// ------------------------- fused LN1 + 7-tap conv + gelu ---------------------------
// LN phase: warp-autonomous (one barrier). Conv phase: packed bf16x2 ring window.
#define TOKB 32
#define CROWS (TOKB + 6)   // 38
__global__ __launch_bounds__(256) void lnconv_kernel(
    const float* __restrict__ x, const float* __restrict__ g, const float* __restrict__ bb,
    const float* __restrict__ w3, const float* __restrict__ b3,
    const float* __restrict__ w5, const float* __restrict__ b5,
    const float* __restrict__ w7, const float* __restrict__ b7,
    bf16* __restrict__ out) {
    extern __shared__ char sm[];
    bf16* s_rows = (bf16*)sm;                         // 38*512 bf16

    const int tid = threadIdx.x;
    const int b = blockIdx.y;
    const int l0 = blockIdx.x * TOKB;

    const int wid = tid >> 5, lane = tid & 31;

    float4 gg[4], bv[4];
#pragma unroll
    for (int j = 0; j < 4; j++) {
        gg[j] = *reinterpret_cast<const float4*>(g + (lane + 32 * j) * 4);
        bv[j] = *reinterpret_cast<const float4*>(bb + (lane + 32 * j) * 4);
    }

    for (int i = wid; i < CROWS; i += 8) {
        int l = l0 - 3 + i;
        bool valid = (l >= 0) && (l < L);
        float4 v[4];
#pragma unroll
        for (int j = 0; j < 4; j++) v[j] = make_float4(0.f, 0.f, 0.f, 0.f);
        if (valid) {
            const float* xr = x + ((size_t)b * L + l) * D;
#pragma unroll
            for (int j = 0; j < 4; j++)
                v[j] = *reinterpret_cast<const float4*>(xr + (lane + 32 * j) * 4);
        }
        float s = 0.f;
#pragma unroll
        for (int j = 0; j < 4; j++) s += v[j].x + v[j].y + v[j].z + v[j].w;
#pragma unroll
        for (int o = 16; o; o >>= 1) s += __shfl_xor_sync(~0u, s, o);
        float mean = s * (1.f / 512.f);
        float s2 = 0.f;
#pragma unroll
        for (int j = 0; j < 4; j++) {
            float dx = v[j].x - mean, dy = v[j].y - mean;
            float dz = v[j].z - mean, dw = v[j].w - mean;
            s2 += dx * dx + dy * dy + dz * dz + dw * dw;
        }
#pragma unroll
        for (int o = 16; o; o >>= 1) s2 += __shfl_xor_sync(~0u, s2, o);
        float rstd = rsqrtf(s2 * (1.f / 512.f) + 1e-5f);
#pragma unroll
        for (int j = 0; j < 4; j++) {
            bf162 o1, o2;
            if (valid) {
                o1.x = __float2bfloat16((v[j].x - mean) * rstd * gg[j].x + bv[j].x);
                o1.y = __float2bfloat16((v[j].y - mean) * rstd * gg[j].y + bv[j].y);
                o2.x = __float2bfloat16((v[j].z - mean) * rstd * gg[j].z + bv[j].z);
                o2.y = __float2bfloat16((v[j].w - mean) * rstd * gg[j].w + bv[j].w);
            } else {
                o1.x = o1.y = o2.x = o2.y = __float2bfloat16(0.f);
            }
            uint2 pk;
            pk.x = *reinterpret_cast<uint32_t*>(&o1);
            pk.y = *reinterpret_cast<uint32_t*>(&o2);
            *reinterpret_cast<uint2*>(s_rows + i * 512 + (lane + 32 * j) * 4) = pk;
        }
    }
    __syncthreads();   // the only block barrier

    // conv phase: thread owns dp pair; packed bf162 taps; 7-row ring window
    const int dp = tid * 2;   // 0..510
    bf162 tap2[7], cb2;
    {
        float cb0 = (b3[dp] + b5[dp] + b7[dp]) * (1.f / 3.f);
        float cb1 = (b3[dp + 1] + b5[dp + 1] + b7[dp + 1]) * (1.f / 3.f);
        cb2 = __floats2bfloat162_rn(cb0, cb1);
#pragma unroll
        for (int j = 0; j < 7; j++) {
            float t0 = w7[dp * 7 + j], t1 = w7[(dp + 1) * 7 + j];
            if (j >= 1 && j <= 5) { t0 += w5[dp * 5 + (j - 1)]; t1 += w5[(dp + 1) * 5 + (j - 1)]; }
            if (j >= 2 && j <= 4) { t0 += w3[dp * 3 + (j - 2)]; t1 += w3[(dp + 1) * 3 + (j - 2)]; }
            tap2[j] = __floats2bfloat162_rn(t0 * (1.f / 3.f), t1 * (1.f / 3.f));
        }
    }
    bf162 w[7];
#pragma unroll
    for (int j = 0; j < 6; j++)
        w[j] = *reinterpret_cast<const bf162*>(s_rows + j * 512 + dp);
    bf16* orow = out + ((size_t)b * L + l0) * D + dp;
#pragma unroll 4
    for (int ti = 0; ti < TOKB; ti++) {
        w[6] = *reinterpret_cast<const bf162*>(s_rows + (ti + 6) * 512 + dp);
        bf162 acc = cb2;
#pragma unroll
        for (int j = 0; j < 7; j++) acc = __hfma2(w[j], tap2[j], acc);
        *reinterpret_cast<bf162*>(orow + (size_t)ti * D) = gelu2(acc);
#pragma unroll
        for (int j = 0; j < 6; j++) w[j] = w[j + 1];
    }
}
#define LNCONV_SMEM (CROWS * 512 * 2)

// ------------------------- LayerNorm (fp32 in -> bf16 out), 2 tokens/block ---------
__global__ __launch_bounds__(256) void ln_kernel(const float* __restrict__ x,
                                                 const float* __restrict__ g,
                                                 const float* __restrict__ bb,
                                                 bf16* __restrict__ out) {
    int half = threadIdx.x >> 7;
    int n = blockIdx.x * 2 + half;
    const float* xr = x + (size_t)n * D;
    int t = threadIdx.x & 127;
    float4 v = *reinterpret_cast<const float4*>(xr + t * 4);
    float s = v.x + v.y + v.z + v.w;
    __shared__ float red[2][4];
#pragma unroll
    for (int o = 16; o; o >>= 1) s += __shfl_xor_sync(~0u, s, o);
    if ((t & 31) == 0) red[half][t >> 5] = s;
    __syncthreads();
    float mean = (red[half][0] + red[half][1] + red[half][2] + red[half][3]) * (1.f / 512.f);
    float dx = v.x - mean, dy = v.y - mean, dz = v.z - mean, dw = v.w - mean;
    float s2 = dx * dx + dy * dy + dz * dz + dw * dw;
#pragma unroll
    for (int o = 16; o; o >>= 1) s2 += __shfl_xor_sync(~0u, s2, o);
    __syncthreads();
    if ((t & 31) == 0) red[half][t >> 5] = s2;
    __syncthreads();
    float rstd = rsqrtf((red[half][0] + red[half][1] + red[half][2] + red[half][3]) *
                            (1.f / 512.f) + 1e-5f);
    float4 gg = *reinterpret_cast<const float4*>(g + t * 4);
    float4 bbv = *reinterpret_cast<const float4*>(bb + t * 4);
    bf162 o1, o2;
    o1.x = __float2bfloat16(dx * rstd * gg.x + bbv.x);
    o1.y = __float2bfloat16(dy * rstd * gg.y + bbv.y);
    o2.x = __float2bfloat16(dz * rstd * gg.z + bbv.z);
    o2.y = __float2bfloat16(dw * rstd * gg.w + bbv.w);
    uint2 pk;
    pk.x = *reinterpret_cast<uint32_t*>(&o1);
    pk.y = *reinterpret_cast<uint32_t*>(&o2);
    *reinterpret_cast<uint2*>(out + (size_t)n * D + t * 4) = pk;
}

// ---------------- weight prep: z0..2 transpose+convert, z3 wmix convert + zero ct --
__global__ void transconv3_kernel(const float* __restrict__ wout,
                                  const float* __restrict__ ffn_w1,
                                  const float* __restrict__ ffn_w2,
                                  const float* __restrict__ wmix,
                                  bf16* __restrict__ woutT, bf16* __restrict__ w1T,
                                  bf16* __restrict__ w2T, bf16* __restrict__ wmixB,
                                  int zoff) {
    int z = blockIdx.z + zoff;
    if (z == 3) {  // plain convert wmix (512x512) + zero g_ct from block (0,0)
        if ((int)blockIdx.x * 32 >= D || (int)blockIdx.y * 32 >= D) return;
        int xx = blockIdx.x * 32 + threadIdx.x;
        int y0 = blockIdx.y * 32 + threadIdx.y;
#pragma unroll
        for (int i = 0; i < 32; i += 8)
            wmixB[(size_t)(y0 + i) * D + xx] = __float2bfloat16(wmix[(size_t)(y0 + i) * D + xx]);
        if (blockIdx.x == 0 && blockIdx.y == 0) {
            int t = threadIdx.y * 32 + threadIdx.x;
            for (int k = t; k < Bsz * D; k += 256) g_ct[k] = 0.f;
        }
        return;
    }
    const float* in;
    bf16* outp;
    int R, C;
    if (z == 0)      { in = wout;   outp = woutT; R = D;   C = D; }
    else if (z == 1) { in = ffn_w1; outp = w1T;   R = D;   C = HID; }
    else             { in = ffn_w2; outp = w2T;   R = HID; C = D; }
    if ((int)blockIdx.x * 32 >= C || (int)blockIdx.y * 32 >= R) return;

    __shared__ float tile[32][33];
    int x = blockIdx.x * 32 + threadIdx.x;
    int y = blockIdx.y * 32 + threadIdx.y;
#pragma unroll
    for (int i = 0; i < 32; i += 8)
        tile[threadIdx.y + i][threadIdx.x] = in[(size_t)(y + i) * C + x];
    __syncthreads();
    int ox = blockIdx.y * 32 + threadIdx.x;
    int oy = blockIdx.x * 32 + threadIdx.y;
#pragma unroll
    for (int i = 0; i < 32; i += 8)
        outp[(size_t)(oy + i) * R + ox] = __float2bfloat16(tile[threadIdx.x][threadIdx.y + i]);
}

// ------------------------- gate MLP (tiny) ------------------------------------------
__global__ void gate_kernel(const float* __restrict__ cg_w1, const float* __restrict__ cg_b1,
                            const float* __restrict__ cg_w2, const float* __restrict__ cg_b2,
                            const float* __restrict__ bmix) {
    int b = blockIdx.x;
    int t = threadIdx.x;
    __shared__ float ct[D];
    __shared__ float hid[GH];
    for (int d = t; d < D; d += 128)
        ct[d] = g_ct[b * D + d] * (1.f / (float)L) + bmix[d];
    __syncthreads();
    {
        float hv = cg_b1[t];
        for (int d = 0; d < D; d++) hv = fmaf(ct[d], cg_w1[d * GH + t], hv);
        hid[t] = gelu_fast(hv);
    }
    __syncthreads();
    for (int o = t; o < D; o += 128) {
        float s = cg_b2[o];
#pragma unroll 4
        for (int j = 0; j < GH; j++) s = fmaf(hid[j], cg_w2[j * D + o], s);
        g_gate[b * D + o] = 1.f / (1.f + expf(-s));
    }
}

// ------------------------- bf16 MMA GEMM 128x128x64, 256 thr, warp 64x32 -----------
// (mainloop unchanged — proven config)
#define ROWB 144
#define TILEB (128 * ROWB)
#define STAGEB (2 * TILEB)
#define SMEMB (2 * STAGEB)

__global__ __launch_bounds__(256, 2) void hgemm_kernel(
    const bf16* __restrict__ A, const bf16* __restrict__ Bw,
    const float* __restrict__ bias, float* __restrict__ Cf, bf16* __restrict__ Cb,
    int M, int Nn, int K, int epi, const float* __restrict__ res,
    const float* __restrict__ scale, const float* __restrict__ gate) {
    extern __shared__ __align__(16) char smem[];

    const int tid = threadIdx.x;
    const int bm = blockIdx.y << 7;
    const int bn = blockIdx.x << 7;
    const uint32_t sbase = smem_u32(smem);

    const int lrow = tid >> 3;
    const int lc = tid & 7;
    auto load_stage = [&](int s, int k0) {
        uint32_t st = sbase + s * STAGEB;
#pragma unroll
        for (int i = 0; i < 4; i++) {
            int row = lrow + i * 32;
            cpasync16(st + row * ROWB + lc * 16, A + (size_t)(bm + row) * K + k0 + lc * 8);
        }
#pragma unroll
        for (int i = 0; i < 4; i++) {
            int row = lrow + i * 32;
            cpasync16(st + TILEB + row * ROWB + lc * 16,
                      Bw + (size_t)(bn + row) * K + k0 + lc * 8);
        }
    };

    const int wid = tid >> 5, lane = tid & 31;
    const int wm = wid & 1;
    const int wn = wid >> 1;

    float acc[4][4][4];
#pragma unroll
    for (int mt = 0; mt < 4; mt++)
#pragma unroll
        for (int nt = 0; nt < 4; nt++)
#pragma unroll
            for (int r = 0; r < 4; r++) acc[mt][nt][r] = 0.f;

    const int KT = K >> 6;
    load_stage(0, 0);
    cp_commit();

    const uint32_t a_off = (wm * 64 + (lane & 15)) * ROWB + (lane >> 4) * 16;
    const uint32_t b_off = TILEB + (wn * 32 + (lane >> 4) * 8 + (lane & 7)) * ROWB +
                           ((lane >> 3) & 1) * 16;
    const int gb = (bm >> 11) * D;

    for (int kt = 0; kt < KT; kt++) {
        int s = kt & 1;
        if (kt + 1 < KT) {
            load_stage(s ^ 1, (kt + 1) << 6);
            cp_commit();
            cp_wait<1>();
        } else {
            cp_wait<0>();
        }
        __syncthreads();
        uint32_t st = sbase + s * STAGEB;
#pragma unroll
        for (int kk = 0; kk < 4; kk++) {
            uint32_t a[4][4], b[2][4];
#pragma unroll
            for (int mt = 0; mt < 4; mt++)
                ldmat4(a[mt], st + a_off + mt * 16 * ROWB + kk * 32);
#pragma unroll
            for (int i = 0; i < 2; i++)
                ldmat4(b[i], st + b_off + i * 16 * ROWB + kk * 32);
            if (gate) {
                int kb = gb + (kt << 6) + kk * 16 + (lane & 3) * 2;
                float2 glo = *reinterpret_cast<const float2*>(gate + kb);
                float2 ghi = *reinterpret_cast<const float2*>(gate + kb + 8);
                bf162 glo2 = __floats2bfloat162_rn(glo.x, glo.y);
                bf162 ghi2 = __floats2bfloat162_rn(ghi.x, ghi.y);
#pragma unroll
                for (int mt = 0; mt < 4; mt++) {
                    a[mt][0] = mulbf2(a[mt][0], glo2);
                    a[mt][1] = mulbf2(a[mt][1], glo2);
                    a[mt][2] = mulbf2(a[mt][2], ghi2);
                    a[mt][3] = mulbf2(a[mt][3], ghi2);
                }
            }
#pragma unroll
            for (int mt = 0; mt < 4; mt++)
#pragma unroll
                for (int nt = 0; nt < 4; nt++)
                    mma16816(acc[mt][nt], a[mt], b[nt >> 1][(nt & 1) * 2],
                             b[nt >> 1][(nt & 1) * 2 + 1]);
        }
        __syncthreads();
    }

    // ---- epilogue ----
    const int qrow = lane >> 2;
    const int qcol = (lane & 3) * 2;
#pragma unroll
    for (int nt = 0; nt < 4; nt++) {
        int col = bn + wn * 32 + nt * 8 + qcol;
        float2 bi = *reinterpret_cast<const float2*>(bias + col);
        float2 sc = make_float2(0.f, 0.f);
        if (epi == 2) sc = *reinterpret_cast<const float2*>(scale + col);
#pragma unroll
        for (int mt = 0; mt < 4; mt++) {
#pragma unroll
            for (int half = 0; half < 2; half++) {
                int row = bm + wm * 64 + mt * 16 + qrow + half * 8;
                size_t off = (size_t)row * Nn + col;
                float v0 = acc[mt][nt][half * 2 + 0] + bi.x;
                float v1 = acc[mt][nt][half * 2 + 1] + bi.y;
                if (epi == 0) {
                    bf162 o;
                    o.x = __float2bfloat16(v0);
                    o.y = __float2bfloat16(v1);
                    *reinterpret_cast<bf162*>(Cb + off) = o;
                } else if (epi == 1) {
                    bf162 v = __floats2bfloat162_rn(v0, v1);
                    *reinterpret_cast<bf162*>(Cb + off) = gelu2(v);
                } else {
                    float2 rv = *reinterpret_cast<const float2*>(res + off);
                    *reinterpret_cast<float2*>(Cf + off) =
                        make_float2(rv.x + v0 * sc.x, rv.y + v1 * sc.y);
                }
            }
        }
        if (epi == 0) {
            float cs0 = 0.f, cs1 = 0.f;
#pragma unroll
            for (int mt = 0; mt < 4; mt++) {
                cs0 += acc[mt][nt][0] + acc[mt][nt][2];
                cs1 += acc[mt][nt][1] + acc[mt][nt][3];
            }
#pragma unroll
            for (int o = 4; o <= 16; o <<= 1) {
                cs0 += __shfl_xor_sync(~0u, cs0, o);
                cs1 += __shfl_xor_sync(~0u, cs1, o);
            }
            if (lane < 4) {
                int b = bm >> 11;
                atomicAdd(&g_ct[b * D + col], cs0);
                atomicAdd(&g_ct[b * D + col + 1], cs1);
            }
        }
    }
}

// ------------------------- host launch ---------------------------------------------
extern "C" void kernel_launch(void* const* d_in, const int* in_sizes, int n_in,
                              void* d_out, int out_size) {
    const float* x      = (const float*)d_in[0];
    const float* ln1_g  = (const float*)d_in[1];
    const float* ln1_b  = (const float*)d_in[2];
    const float* w3     = (const float*)d_in[3];
    const float* b3     = (const float*)d_in[4];
    const float* w5     = (const float*)d_in[5];
    const float* b5     = (const float*)d_in[6];
    const float* w7     = (const float*)d_in[7];
    const float* b7     = (const float*)d_in[8];
    const float* wmix   = (const float*)d_in[9];
    const float* bmix   = (const float*)d_in[10];
    const float* cg_w1  = (const float*)d_in[11];
    const float* cg_b1  = (const float*)d_in[12];
    const float* cg_w2  = (const float*)d_in[13];
    const float* cg_b2  = (const float*)d_in[14];
    const float* wout   = (const float*)d_in[15];
    const float* bout   = (const float*)d_in[16];
    const float* ls1    = (const float*)d_in[17];
    const float* ln2_g  = (const float*)d_in[18];
    const float* ln2_b  = (const float*)d_in[19];
    const float* ffn_w1 = (const float*)d_in[20];
    const float* ffn_b1 = (const float*)d_in[21];
    const float* ffn_w2 = (const float*)d_in[22];
    const float* ffn_b2 = (const float*)d_in[23];
    const float* ls2    = (const float*)d_in[24];
    float* out = (float*)d_out;

    void* p;
    cudaGetSymbolAddress(&p, g_h);     bf16* hbuf  = (bf16*)p;
    cudaGetSymbolAddress(&p, g_gm);    bf16* gmbuf = (bf16*)p;
    cudaGetSymbolAddress(&p, g_m2);    bf16* m2buf = (bf16*)p;
    cudaGetSymbolAddress(&p, g_x1);    float* x1buf = (float*)p;
    cudaGetSymbolAddress(&p, g_t);     bf16* tbuf  = (bf16*)p;
    cudaGetSymbolAddress(&p, g_wmixB); bf16* wmixB = (bf16*)p;
    cudaGetSymbolAddress(&p, g_woutT); bf16* woutT = (bf16*)p;
    cudaGetSymbolAddress(&p, g_w1T);   bf16* w1T   = (bf16*)p;
    cudaGetSymbolAddress(&p, g_w2T);   bf16* w2T   = (bf16*)p;
    cudaGetSymbolAddress(&p, g_gate);  float* gate = (float*)p;

    cudaFuncSetAttribute(hgemm_kernel, cudaFuncAttributeMaxDynamicSharedMemorySize, SMEMB);
    cudaFuncSetAttribute(lnconv_kernel, cudaFuncAttributeMaxDynamicSharedMemorySize,
                         LNCONV_SMEM);

    // launch order: lnconv at index 3 (ncu captures launch index 3)
    transconv3_kernel<<<dim3(HID / 32, D / 32, 2), dim3(32, 8)>>>(          // 0 (wout, ffn_w1)
        wout, ffn_w1, ffn_w2, wmix, woutT, w1T, w2T, wmixB, 0);
    transconv3_kernel<<<dim3(D / 32, HID / 32, 1), dim3(32, 8)>>>(          // 1 (ffn_w2)
        wout, ffn_w1, ffn_w2, wmix, woutT, w1T, w2T, wmixB, 2);
    transconv3_kernel<<<dim3(D / 32, D / 32, 1), dim3(32, 8)>>>(            // 2 (wmix + zero ct)
        wout, ffn_w1, ffn_w2, wmix, woutT, w1T, w2T, wmixB, 3);
    lnconv_kernel<<<dim3(L / TOKB, Bsz), 256, LNCONV_SMEM>>>(               // 3 (profiled)
        x, ln1_g, ln1_b, w3, b3, w5, b5, w7, b7, gmbuf);
    hgemm_kernel<<<dim3(D / 128, NTOK / 128), 256, SMEMB>>>(                // 4
        gmbuf, wmixB, bmix, nullptr, m2buf, NTOK, D, D, 0, nullptr, nullptr, nullptr);
    gate_kernel<<<Bsz, 128>>>(cg_w1, cg_b1, cg_w2, cg_b2, bmix);            // 5
    hgemm_kernel<<<dim3(D / 128, NTOK / 128), 256, SMEMB>>>(                // 6
        m2buf, woutT, bout, x1buf, nullptr, NTOK, D, D, 2, x, ls1, gate);
    ln_kernel<<<NTOK / 2, 256>>>(x1buf, ln2_g, ln2_b, hbuf);                // 7
    hgemm_kernel<<<dim3(HID / 128, NTOK / 128), 256, SMEMB>>>(              // 8
        hbuf, w1T, ffn_b1, nullptr, tbuf, NTOK, HID, D, 1, nullptr, nullptr, nullptr);
    hgemm_kernel<<<dim3(D / 128, NTOK / 128), 256, SMEMB>>>(                // 9
        tbuf, w2T, ffn_b2, out, nullptr, NTOK, D, HID, 2, x1buf, ls2, nullptr);
}

// round 13
// speedup vs baseline: 1.0203x; 1.0203x over previous
#include <cuda_runtime.h>
#include <cuda_bf16.h>
#include <math.h>
#include <stdint.h>

#define D 512
#define Bsz 16
#define L 2048
#define HID 2048
#define GH 128
#define NTOK (Bsz * L)   // 32768

typedef __nv_bfloat16 bf16;
typedef __nv_bfloat162 bf162;

// ------------------------- scratch (static device globals) -------------------------
__device__ bf16  g_h[(size_t)NTOK * D];    // ln2 out
__device__ bf16  g_gm[(size_t)NTOK * D];   // gelu(conv mix)
__device__ bf16  g_m2[(size_t)NTOK * D];   // mixed2
__device__ float g_x1[(size_t)NTOK * D];   // first residual out
__device__ bf16  g_t[(size_t)NTOK * HID];  // ffn hidden
__device__ bf16  g_wmixB[D * D];
__device__ bf16  g_woutT[D * D];
__device__ bf16  g_w1T[HID * D];
__device__ bf16  g_w2T[D * HID];
__device__ float g_ct[Bsz * D];            // column sums (atomic)
__device__ float g_gate[Bsz * D];

// fast tanh-form GELU, scalar fp32 (deviation ~1e-3 vs erf; attenuated downstream)
__device__ __forceinline__ float gelu_fast(float v) {
    float t = v * (1.5957692f + 0.07135481f * v * v);
    return __fdividef(v, 1.0f + __expf(-t));
}
__device__ __forceinline__ uint32_t smem_u32(const void* p) {
    uint32_t a;
    asm("{ .reg .u64 t; cvta.to.shared.u64 t, %1; cvt.u32.u64 %0, t; }" : "=r"(a) : "l"(p));
    return a;
}
__device__ __forceinline__ void cpasync16(uint32_t s, const void* g) {
    asm volatile("cp.async.cg.shared.global [%0], [%1], 16;" :: "r"(s), "l"(g));
}
__device__ __forceinline__ void cp_commit() { asm volatile("cp.async.commit_group;"); }
template <int N>
__device__ __forceinline__ void cp_wait() {
    asm volatile("cp.async.wait_group %0;" :: "n"(N));
}
__device__ __forceinline__ void ldmat4(uint32_t* r, uint32_t addr) {
    asm volatile("ldmatrix.sync.aligned.m8n8.x4.shared.b16 {%0,%1,%2,%3}, [%4];"
                 : "=r"(r[0]), "=r"(r[1]), "=r"(r[2]), "=r"(r[3]) : "r"(addr));
}
__device__ __forceinline__ void mma16816(float* c, const uint32_t* a, uint32_t b0,
                                         uint32_t b1) {
    asm volatile(
        "mma.sync.aligned.m16n8k16.row.col.f32.bf16.bf16.f32 "
        "{%0,%1,%2,%3}, {%4,%5,%6,%7}, {%8,%9}, {%0,%1,%2,%3};"
        : "+f"(c[0]), "+f"(c[1]), "+f"(c[2]), "+f"(c[3])
        : "r"(a[0]), "r"(a[1]), "r"(a[2]), "r"(a[3]), "r"(b0), "r"(b1));
}
__device__ __forceinline__ uint32_t mulbf2(uint32_t x, bf162 g) {
    bf162 v = *reinterpret_cast<bf162*>(&x);
    v = __hmul2(v, g);
    return *reinterpret_cast<uint32_t*>(&v);
}

// ------------------------- fused LN1 + 7-tap conv + gelu (R11 proven version) ------
#define TOKB 32
#define CROWS (TOKB + 6)   // 38
__global__ __launch_bounds__(256) void lnconv_kernel(
    const float* __restrict__ x, const float* __restrict__ g, const float* __restrict__ bb,
    const float* __restrict__ w3, const float* __restrict__ b3,
    const float* __restrict__ w5, const float* __restrict__ b5,
    const float* __restrict__ w7, const float* __restrict__ b7,
    bf16* __restrict__ out) {
    extern __shared__ char sm[];
    bf16* s_rows = (bf16*)sm;                         // 38*512 bf16

    const int tid = threadIdx.x;
    const int b = blockIdx.y;
    const int l0 = blockIdx.x * TOKB;

    const int wid = tid >> 5, lane = tid & 31;

    float4 gg[4], bv[4];
#pragma unroll
    for (int j = 0; j < 4; j++) {
        gg[j] = *reinterpret_cast<const float4*>(g + (lane + 32 * j) * 4);
        bv[j] = *reinterpret_cast<const float4*>(bb + (lane + 32 * j) * 4);
    }

    for (int i = wid; i < CROWS; i += 8) {
        int l = l0 - 3 + i;
        bool valid = (l >= 0) && (l < L);
        float4 v[4];
#pragma unroll
        for (int j = 0; j < 4; j++) v[j] = make_float4(0.f, 0.f, 0.f, 0.f);
        if (valid) {
            const float* xr = x + ((size_t)b * L + l) * D;
#pragma unroll
            for (int j = 0; j < 4; j++)
                v[j] = *reinterpret_cast<const float4*>(xr + (lane + 32 * j) * 4);
        }
        float s = 0.f;
#pragma unroll
        for (int j = 0; j < 4; j++) s += v[j].x + v[j].y + v[j].z + v[j].w;
#pragma unroll
        for (int o = 16; o; o >>= 1) s += __shfl_xor_sync(~0u, s, o);
        float mean = s * (1.f / 512.f);
        float s2 = 0.f;
#pragma unroll
        for (int j = 0; j < 4; j++) {
            float dx = v[j].x - mean, dy = v[j].y - mean;
            float dz = v[j].z - mean, dw = v[j].w - mean;
            s2 += dx * dx + dy * dy + dz * dz + dw * dw;
        }
#pragma unroll
        for (int o = 16; o; o >>= 1) s2 += __shfl_xor_sync(~0u, s2, o);
        float rstd = rsqrtf(s2 * (1.f / 512.f) + 1e-5f);
#pragma unroll
        for (int j = 0; j < 4; j++) {
            bf162 o1, o2;
            if (valid) {
                o1.x = __float2bfloat16((v[j].x - mean) * rstd * gg[j].x + bv[j].x);
                o1.y = __float2bfloat16((v[j].y - mean) * rstd * gg[j].y + bv[j].y);
                o2.x = __float2bfloat16((v[j].z - mean) * rstd * gg[j].z + bv[j].z);
                o2.y = __float2bfloat16((v[j].w - mean) * rstd * gg[j].w + bv[j].w);
            } else {
                o1.x = o1.y = o2.x = o2.y = __float2bfloat16(0.f);
            }
            uint2 pk;
            pk.x = *reinterpret_cast<uint32_t*>(&o1);
            pk.y = *reinterpret_cast<uint32_t*>(&o2);
            *reinterpret_cast<uint2*>(s_rows + i * 512 + (lane + 32 * j) * 4) = pk;
        }
    }
    __syncthreads();   // the only block barrier

    // conv phase: thread owns dp pair; fp32 taps in registers; 7-row ring window
    const int dp = tid * 2;   // 0..510
    float tap0[7], tap1[7], cb0, cb1;
    {
        cb0 = (b3[dp] + b5[dp] + b7[dp]) * (1.f / 3.f);
        cb1 = (b3[dp + 1] + b5[dp + 1] + b7[dp + 1]) * (1.f / 3.f);
#pragma unroll
        for (int j = 0; j < 7; j++) {
            float t0 = w7[dp * 7 + j], t1 = w7[(dp + 1) * 7 + j];
            if (j >= 1 && j <= 5) { t0 += w5[dp * 5 + (j - 1)]; t1 += w5[(dp + 1) * 5 + (j - 1)]; }
            if (j >= 2 && j <= 4) { t0 += w3[dp * 3 + (j - 2)]; t1 += w3[(dp + 1) * 3 + (j - 2)]; }
            tap0[j] = t0 * (1.f / 3.f);
            tap1[j] = t1 * (1.f / 3.f);
        }
    }
    bf162 w[7];
#pragma unroll
    for (int j = 0; j < 6; j++)
        w[j] = *reinterpret_cast<const bf162*>(s_rows + j * 512 + dp);
    bf16* orow = out + ((size_t)b * L + l0) * D + dp;
#pragma unroll 4
    for (int ti = 0; ti < TOKB; ti++) {
        w[6] = *reinterpret_cast<const bf162*>(s_rows + (ti + 6) * 512 + dp);
        float ax = cb0, ay = cb1;
#pragma unroll
        for (int j = 0; j < 7; j++) {
            ax = fmaf(__bfloat162float(w[j].x), tap0[j], ax);
            ay = fmaf(__bfloat162float(w[j].y), tap1[j], ay);
        }
        bf162 o;
        o.x = __float2bfloat16(gelu_fast(ax));
        o.y = __float2bfloat16(gelu_fast(ay));
        *reinterpret_cast<bf162*>(orow + (size_t)ti * D) = o;
#pragma unroll
        for (int j = 0; j < 6; j++) w[j] = w[j + 1];
    }
}
#define LNCONV_SMEM (CROWS * 512 * 2)

// ------------------------- LayerNorm LN2: warp-per-token, no block barriers --------
__global__ __launch_bounds__(256) void ln_kernel(const float* __restrict__ x,
                                                 const float* __restrict__ g,
                                                 const float* __restrict__ bb,
                                                 bf16* __restrict__ out) {
    const int wid = threadIdx.x >> 5, lane = threadIdx.x & 31;
    const int n = blockIdx.x * 8 + wid;
    const float* xr = x + (size_t)n * D;

    float4 v[4];
#pragma unroll
    for (int j = 0; j < 4; j++)
        v[j] = *reinterpret_cast<const float4*>(xr + (lane + 32 * j) * 4);
    float s = 0.f;
#pragma unroll
    for (int j = 0; j < 4; j++) s += v[j].x + v[j].y + v[j].z + v[j].w;
#pragma unroll
    for (int o = 16; o; o >>= 1) s += __shfl_xor_sync(~0u, s, o);
    float mean = s * (1.f / 512.f);
    float s2 = 0.f;
#pragma unroll
    for (int j = 0; j < 4; j++) {
        float dx = v[j].x - mean, dy = v[j].y - mean;
        float dz = v[j].z - mean, dw = v[j].w - mean;
        s2 += dx * dx + dy * dy + dz * dz + dw * dw;
    }
#pragma unroll
    for (int o = 16; o; o >>= 1) s2 += __shfl_xor_sync(~0u, s2, o);
    float rstd = rsqrtf(s2 * (1.f / 512.f) + 1e-5f);
#pragma unroll
    for (int j = 0; j < 4; j++) {
        float4 gg = *reinterpret_cast<const float4*>(g + (lane + 32 * j) * 4);
        float4 bv = *reinterpret_cast<const float4*>(bb + (lane + 32 * j) * 4);
        bf162 o1, o2;
        o1.x = __float2bfloat16((v[j].x - mean) * rstd * gg.x + bv.x);
        o1.y = __float2bfloat16((v[j].y - mean) * rstd * gg.y + bv.y);
        o2.x = __float2bfloat16((v[j].z - mean) * rstd * gg.z + bv.z);
        o2.y = __float2bfloat16((v[j].w - mean) * rstd * gg.w + bv.w);
        uint2 pk;
        pk.x = *reinterpret_cast<uint32_t*>(&o1);
        pk.y = *reinterpret_cast<uint32_t*>(&o2);
        *reinterpret_cast<uint2*>(out + (size_t)n * D + (lane + 32 * j) * 4) = pk;
    }
}

// ---------------- weight prep: z0..2 transpose+convert, z3 wmix convert + zero ct --
__global__ void transconv3_kernel(const float* __restrict__ wout,
                                  const float* __restrict__ ffn_w1,
                                  const float* __restrict__ ffn_w2,
                                  const float* __restrict__ wmix,
                                  bf16* __restrict__ woutT, bf16* __restrict__ w1T,
                                  bf16* __restrict__ w2T, bf16* __restrict__ wmixB,
                                  int zoff) {
    int z = blockIdx.z + zoff;
    if (z == 3) {  // plain convert wmix (512x512) + zero g_ct from block (0,0)
        if ((int)blockIdx.x * 32 >= D || (int)blockIdx.y * 32 >= D) return;
        int xx = blockIdx.x * 32 + threadIdx.x;
        int y0 = blockIdx.y * 32 + threadIdx.y;
#pragma unroll
        for (int i = 0; i < 32; i += 8)
            wmixB[(size_t)(y0 + i) * D + xx] = __float2bfloat16(wmix[(size_t)(y0 + i) * D + xx]);
        if (blockIdx.x == 0 && blockIdx.y == 0) {
            int t = threadIdx.y * 32 + threadIdx.x;
            for (int k = t; k < Bsz * D; k += 256) g_ct[k] = 0.f;
        }
        return;
    }
    const float* in;
    bf16* outp;
    int R, C;
    if (z == 0)      { in = wout;   outp = woutT; R = D;   C = D; }
    else if (z == 1) { in = ffn_w1; outp = w1T;   R = D;   C = HID; }
    else             { in = ffn_w2; outp = w2T;   R = HID; C = D; }
    if ((int)blockIdx.x * 32 >= C || (int)blockIdx.y * 32 >= R) return;

    __shared__ float tile[32][33];
    int x = blockIdx.x * 32 + threadIdx.x;
    int y = blockIdx.y * 32 + threadIdx.y;
#pragma unroll
    for (int i = 0; i < 32; i += 8)
        tile[threadIdx.y + i][threadIdx.x] = in[(size_t)(y + i) * C + x];
    __syncthreads();
    int ox = blockIdx.y * 32 + threadIdx.x;
    int oy = blockIdx.x * 32 + threadIdx.y;
#pragma unroll
    for (int i = 0; i < 32; i += 8)
        outp[(size_t)(oy + i) * R + ox] = __float2bfloat16(tile[threadIdx.x][threadIdx.y + i]);
}

// ------------------------- gate MLP (tiny) ------------------------------------------
__global__ void gate_kernel(const float* __restrict__ cg_w1, const float* __restrict__ cg_b1,
                            const float* __restrict__ cg_w2, const float* __restrict__ cg_b2,
                            const float* __restrict__ bmix) {
    int b = blockIdx.x;
    int t = threadIdx.x;
    __shared__ float ct[D];
    __shared__ float hid[GH];
    for (int d = t; d < D; d += 128)
        ct[d] = g_ct[b * D + d] * (1.f / (float)L) + bmix[d];
    __syncthreads();
    {
        float hv = cg_b1[t];
        for (int d = 0; d < D; d++) hv = fmaf(ct[d], cg_w1[d * GH + t], hv);
        hid[t] = gelu_fast(hv);
    }
    __syncthreads();
    for (int o = t; o < D; o += 128) {
        float s = cg_b2[o];
#pragma unroll 4
        for (int j = 0; j < GH; j++) s = fmaf(hid[j], cg_w2[j * D + o], s);
        g_gate[b * D + o] = 1.f / (1.f + expf(-s));
    }
}

// ------------------------- bf16 MMA GEMM 128x128x64, 256 thr, warp 64x32 -----------
// (mainloop unchanged — proven config)
#define ROWB 144
#define TILEB (128 * ROWB)
#define STAGEB (2 * TILEB)
#define SMEMB (2 * STAGEB)

__global__ __launch_bounds__(256, 2) void hgemm_kernel(
    const bf16* __restrict__ A, const bf16* __restrict__ Bw,
    const float* __restrict__ bias, float* __restrict__ Cf, bf16* __restrict__ Cb,
    int M, int Nn, int K, int epi, const float* __restrict__ res,
    const float* __restrict__ scale, const float* __restrict__ gate) {
    extern __shared__ __align__(16) char smem[];

    const int tid = threadIdx.x;
    const int bm = blockIdx.y << 7;
    const int bn = blockIdx.x << 7;
    const uint32_t sbase = smem_u32(smem);

    const int lrow = tid >> 3;
    const int lc = tid & 7;
    auto load_stage = [&](int s, int k0) {
        uint32_t st = sbase + s * STAGEB;
#pragma unroll
        for (int i = 0; i < 4; i++) {
            int row = lrow + i * 32;
            cpasync16(st + row * ROWB + lc * 16, A + (size_t)(bm + row) * K + k0 + lc * 8);
        }
#pragma unroll
        for (int i = 0; i < 4; i++) {
            int row = lrow + i * 32;
            cpasync16(st + TILEB + row * ROWB + lc * 16,
                      Bw + (size_t)(bn + row) * K + k0 + lc * 8);
        }
    };

    const int wid = tid >> 5, lane = tid & 31;
    const int wm = wid & 1;
    const int wn = wid >> 1;

    float acc[4][4][4];
#pragma unroll
    for (int mt = 0; mt < 4; mt++)
#pragma unroll
        for (int nt = 0; nt < 4; nt++)
#pragma unroll
            for (int r = 0; r < 4; r++) acc[mt][nt][r] = 0.f;

    const int KT = K >> 6;
    load_stage(0, 0);
    cp_commit();

    const uint32_t a_off = (wm * 64 + (lane & 15)) * ROWB + (lane >> 4) * 16;
    const uint32_t b_off = TILEB + (wn * 32 + (lane >> 4) * 8 + (lane & 7)) * ROWB +
                           ((lane >> 3) & 1) * 16;
    const int gb = (bm >> 11) * D;

    for (int kt = 0; kt < KT; kt++) {
        int s = kt & 1;
        if (kt + 1 < KT) {
            load_stage(s ^ 1, (kt + 1) << 6);
            cp_commit();
            cp_wait<1>();
        } else {
            cp_wait<0>();
        }
        __syncthreads();
        uint32_t st = sbase + s * STAGEB;
#pragma unroll
        for (int kk = 0; kk < 4; kk++) {
            uint32_t a[4][4], b[2][4];
#pragma unroll
            for (int mt = 0; mt < 4; mt++)
                ldmat4(a[mt], st + a_off + mt * 16 * ROWB + kk * 32);
#pragma unroll
            for (int i = 0; i < 2; i++)
                ldmat4(b[i], st + b_off + i * 16 * ROWB + kk * 32);
            if (gate) {
                int kb = gb + (kt << 6) + kk * 16 + (lane & 3) * 2;
                float2 glo = *reinterpret_cast<const float2*>(gate + kb);
                float2 ghi = *reinterpret_cast<const float2*>(gate + kb + 8);
                bf162 glo2 = __floats2bfloat162_rn(glo.x, glo.y);
                bf162 ghi2 = __floats2bfloat162_rn(ghi.x, ghi.y);
#pragma unroll
                for (int mt = 0; mt < 4; mt++) {
                    a[mt][0] = mulbf2(a[mt][0], glo2);
                    a[mt][1] = mulbf2(a[mt][1], glo2);
                    a[mt][2] = mulbf2(a[mt][2], ghi2);
                    a[mt][3] = mulbf2(a[mt][3], ghi2);
                }
            }
#pragma unroll
            for (int mt = 0; mt < 4; mt++)
#pragma unroll
                for (int nt = 0; nt < 4; nt++)
                    mma16816(acc[mt][nt], a[mt], b[nt >> 1][(nt & 1) * 2],
                             b[nt >> 1][(nt & 1) * 2 + 1]);
        }
        __syncthreads();
    }

    // ---- epilogue ----
    const int qrow = lane >> 2;
    const int qcol = (lane & 3) * 2;
#pragma unroll
    for (int nt = 0; nt < 4; nt++) {
        int col = bn + wn * 32 + nt * 8 + qcol;
        float2 bi = *reinterpret_cast<const float2*>(bias + col);
        float2 sc = make_float2(0.f, 0.f);
        if (epi == 2) sc = *reinterpret_cast<const float2*>(scale + col);
#pragma unroll
        for (int mt = 0; mt < 4; mt++) {
#pragma unroll
            for (int half = 0; half < 2; half++) {
                int row = bm + wm * 64 + mt * 16 + qrow + half * 8;
                size_t off = (size_t)row * Nn + col;
                float v0 = acc[mt][nt][half * 2 + 0] + bi.x;
                float v1 = acc[mt][nt][half * 2 + 1] + bi.y;
                if (epi == 0) {
                    bf162 o;
                    o.x = __float2bfloat16(v0);
                    o.y = __float2bfloat16(v1);
                    *reinterpret_cast<bf162*>(Cb + off) = o;
                } else if (epi == 1) {
                    bf162 o;
                    o.x = __float2bfloat16(gelu_fast(v0));
                    o.y = __float2bfloat16(gelu_fast(v1));
                    *reinterpret_cast<bf162*>(Cb + off) = o;
                } else {
                    float2 rv = *reinterpret_cast<const float2*>(res + off);
                    *reinterpret_cast<float2*>(Cf + off) =
                        make_float2(rv.x + v0 * sc.x, rv.y + v1 * sc.y);
                }
            }
        }
        if (epi == 0) {
            float cs0 = 0.f, cs1 = 0.f;
#pragma unroll
            for (int mt = 0; mt < 4; mt++) {
                cs0 += acc[mt][nt][0] + acc[mt][nt][2];
                cs1 += acc[mt][nt][1] + acc[mt][nt][3];
            }
#pragma unroll
            for (int o = 4; o <= 16; o <<= 1) {
                cs0 += __shfl_xor_sync(~0u, cs0, o);
                cs1 += __shfl_xor_sync(~0u, cs1, o);
            }
            if (lane < 4) {
                int b = bm >> 11;
                atomicAdd(&g_ct[b * D + col], cs0);
                atomicAdd(&g_ct[b * D + col + 1], cs1);
            }
        }
    }
}

// ------------------------- host launch ---------------------------------------------
extern "C" void kernel_launch(void* const* d_in, const int* in_sizes, int n_in,
                              void* d_out, int out_size) {
    const float* x      = (const float*)d_in[0];
    const float* ln1_g  = (const float*)d_in[1];
    const float* ln1_b  = (const float*)d_in[2];
    const float* w3     = (const float*)d_in[3];
    const float* b3     = (const float*)d_in[4];
    const float* w5     = (const float*)d_in[5];
    const float* b5     = (const float*)d_in[6];
    const float* w7     = (const float*)d_in[7];
    const float* b7     = (const float*)d_in[8];
    const float* wmix   = (const float*)d_in[9];
    const float* bmix   = (const float*)d_in[10];
    const float* cg_w1  = (const float*)d_in[11];
    const float* cg_b1  = (const float*)d_in[12];
    const float* cg_w2  = (const float*)d_in[13];
    const float* cg_b2  = (const float*)d_in[14];
    const float* wout   = (const float*)d_in[15];
    const float* bout   = (const float*)d_in[16];
    const float* ls1    = (const float*)d_in[17];
    const float* ln2_g  = (const float*)d_in[18];
    const float* ln2_b  = (const float*)d_in[19];
    const float* ffn_w1 = (const float*)d_in[20];
    const float* ffn_b1 = (const float*)d_in[21];
    const float* ffn_w2 = (const float*)d_in[22];
    const float* ffn_b2 = (const float*)d_in[23];
    const float* ls2    = (const float*)d_in[24];
    float* out = (float*)d_out;

    void* p;
    cudaGetSymbolAddress(&p, g_h);     bf16* hbuf  = (bf16*)p;
    cudaGetSymbolAddress(&p, g_gm);    bf16* gmbuf = (bf16*)p;
    cudaGetSymbolAddress(&p, g_m2);    bf16* m2buf = (bf16*)p;
    cudaGetSymbolAddress(&p, g_x1);    float* x1buf = (float*)p;
    cudaGetSymbolAddress(&p, g_t);     bf16* tbuf  = (bf16*)p;
    cudaGetSymbolAddress(&p, g_wmixB); bf16* wmixB = (bf16*)p;
    cudaGetSymbolAddress(&p, g_woutT); bf16* woutT = (bf16*)p;
    cudaGetSymbolAddress(&p, g_w1T);   bf16* w1T   = (bf16*)p;
    cudaGetSymbolAddress(&p, g_w2T);   bf16* w2T   = (bf16*)p;
    cudaGetSymbolAddress(&p, g_gate);  float* gate = (float*)p;

    cudaFuncSetAttribute(hgemm_kernel, cudaFuncAttributeMaxDynamicSharedMemorySize, SMEMB);
    cudaFuncSetAttribute(lnconv_kernel, cudaFuncAttributeMaxDynamicSharedMemorySize,
                         LNCONV_SMEM);

    // launch order: gemm1 at index 3 (ncu captures launch index 3)
    transconv3_kernel<<<dim3(HID / 32, D / 32, 2), dim3(32, 8)>>>(          // 0 (wout, ffn_w1)
        wout, ffn_w1, ffn_w2, wmix, woutT, w1T, w2T, wmixB, 0);
    transconv3_kernel<<<dim3(D / 32, HID / 32, 2), dim3(32, 8)>>>(          // 1 (ffn_w2, wmix+ct)
        wout, ffn_w1, ffn_w2, wmix, woutT, w1T, w2T, wmixB, 2);
    lnconv_kernel<<<dim3(L / TOKB, Bsz), 256, LNCONV_SMEM>>>(               // 2
        x, ln1_g, ln1_b, w3, b3, w5, b5, w7, b7, gmbuf);
    hgemm_kernel<<<dim3(D / 128, NTOK / 128), 256, SMEMB>>>(                // 3 (profiled)
        gmbuf, wmixB, bmix, nullptr, m2buf, NTOK, D, D, 0, nullptr, nullptr, nullptr);
    gate_kernel<<<Bsz, 128>>>(cg_w1, cg_b1, cg_w2, cg_b2, bmix);            // 4
    hgemm_kernel<<<dim3(D / 128, NTOK / 128), 256, SMEMB>>>(                // 5
        m2buf, woutT, bout, x1buf, nullptr, NTOK, D, D, 2, x, ls1, gate);
    ln_kernel<<<NTOK / 8, 256>>>(x1buf, ln2_g, ln2_b, hbuf);                // 6
    hgemm_kernel<<<dim3(HID / 128, NTOK / 128), 256, SMEMB>>>(              // 7
        hbuf, w1T, ffn_b1, nullptr, tbuf, NTOK, HID, D, 1, nullptr, nullptr, nullptr);
    hgemm_kernel<<<dim3(D / 128, NTOK / 128), 256, SMEMB>>>(                // 8
        tbuf, w2T, ffn_b2, out, nullptr, NTOK, D, HID, 2, x1buf, ls2, nullptr);
}